// round 8
// baseline (speedup 1.0000x reference)
#include <cuda_runtime.h>

#define Bc 8
#define Pc 512
#define Dc 16
#define Ec 64
#define Hc 128

typedef unsigned long long u64;

// Scratch (no allocations allowed -> __device__ globals)
__device__ float g_a[Bc * Pc * Hc];     // a_s = ns @ We1[17:33]          (2 MB)
__device__ float g_c[Bc * Pc * Hc];     // c_r = nr @ We1[1:17] + be1     (2 MB)
__device__ float g_dist[Bc * Pc * Pc];  // dist[b][r][s]                  (8 MB)

// ---------------- packed f32x2 helpers (sm_103a) ----------------
__device__ __forceinline__ u64 add2(u64 a, u64 b) {
    u64 r; asm("add.rn.f32x2 %0,%1,%2;" : "=l"(r) : "l"(a), "l"(b)); return r;
}
__device__ __forceinline__ u64 fma2(u64 a, u64 b, u64 c) {
    u64 r; asm("fma.rn.f32x2 %0,%1,%2,%3;" : "=l"(r) : "l"(a), "l"(b), "l"(c)); return r;
}
__device__ __forceinline__ u64 pack2(float lo, float hi) {
    u64 r; asm("mov.b64 %0,{%1,%2};" : "=l"(r) : "f"(lo), "f"(hi)); return r;
}
__device__ __forceinline__ void unpack2(u64 x, float& lo, float& hi) {
    asm("mov.b64 {%0,%1},%2;" : "=f"(lo), "=f"(hi) : "l"(x));
}
__device__ __forceinline__ u64 relu2(u64 x) {
    float lo, hi; unpack2(x, lo, hi);
    return pack2(fmaxf(lo, 0.f), fmaxf(hi, 0.f));
}

// ---------------------------------------------------------------------------
// K1 (fused pre+dist): grid = (b, 16-receiver chunk) = 8*32, 256 threads.
// ---------------------------------------------------------------------------
__global__ void __launch_bounds__(256)
predist_kernel(const float* __restrict__ h,
               const float* __restrict__ We1,
               const float* __restrict__ be1) {
    int b = blockIdx.x >> 5;
    int rc = blockIdx.x & 31;
    int t = threadIdx.x;

    __shared__ float nd[Pc][Dc + 1];  // 34.8 KB, pad kills conflicts

    for (int i = t; i < Pc * Dc; i += 256)
        nd[i >> 4][i & 15] = h[b * Pc * Dc + i];
    __syncthreads();

    // ---- a, c for nodes rc*16 .. rc*16+15 ----
    {
        int k = t & 127;
        int ng = t >> 7;               // 0/1 -> 8 nodes each
        int n0 = rc * 16 + ng * 8;
        float a[8], c[8];
        float b1 = be1[k];
#pragma unroll
        for (int n = 0; n < 8; n++) { a[n] = 0.f; c[n] = b1; }
#pragma unroll
        for (int d = 0; d < Dc; d++) {
            float ws = We1[(17 + d) * Hc + k];
            float wr = We1[(1 + d) * Hc + k];
#pragma unroll
            for (int n = 0; n < 8; n++) {
                float x = nd[n0 + n][d];
                a[n] = fmaf(x, ws, a[n]);
                c[n] = fmaf(x, wr, c[n]);
            }
        }
#pragma unroll
        for (int n = 0; n < 8; n++) {
            g_a[(b * Pc + n0 + n) * Hc + k] = a[n];
            g_c[(b * Pc + n0 + n) * Hc + k] = c[n];
        }
    }

    // ---- dist rows: 16 receivers x 512 senders ----
    for (int idx = t; idx < 16 * Pc; idx += 256) {
        int r = rc * 16 + (idx >> 9);
        int s = idx & (Pc - 1);
        float acc = 0.f;
#pragma unroll
        for (int d = 0; d < Dc; d++) {
            float df = nd[r][d] - nd[s][d];
            acc = fmaf(df, df, acc);
        }
        g_dist[(b * Pc + r) * Pc + s] = sqrtf(acc);
    }
}

// ---------------------------------------------------------------------------
// K2 (fused edge+post): grid = 512 (b, 8 receivers), 256 threads.
// Thread = (sender-half hf[0..1], recv-group rg[0..1], k-pair kp[0..63]).
// 5 CTAs/SM (40 warps) via slim 51-reg threads; av is a native LDG.64 u64
// (no pack); dist pairs via LDS.128 broadcast; branch-free depth-2 prefetch.
// ---------------------------------------------------------------------------
__global__ void __launch_bounds__(256, 5)
edgepost_kernel(const float* __restrict__ h,
                const float* __restrict__ We1,
                const float* __restrict__ We2,
                const float* __restrict__ be2,
                const float* __restrict__ Wn1,
                const float* __restrict__ bn1,
                const float* __restrict__ Wn2,
                const float* __restrict__ bn2,
                float* __restrict__ out) {
    int b = blockIdx.x >> 6;
    int r0 = (blockIdx.x & 63) * 8;
    int node0 = b * Pc + r0;
    int t = threadIdx.x;
    int kp = t & 63;           // k-pair: k = 2*kp, 2*kp+1
    int rg = (t >> 6) & 1;     // receiver group (4 each)
    int hf = t >> 7;           // sender half (256 each)
    int k0 = kp * 2;

    __shared__ __align__(16) u64 sbig[8 * Pc];    // 32 KB: dist tile -> partials/nin/hid
#define PBUF(hh, r, x) sbig[(((hh) * 8 + (r)) << 6) + (x)]
    __shared__ __align__(16) float Hs[8][Hc];     // 4 KB
    float* nin = (float*)((char*)sbig + 8192);    // 8 x 80 floats (2.5 KB), past PBUF
    float* hid = (float*)((char*)sbig + 8192 + 2560);  // 8 x 128 floats (4 KB)

    u64 w0 = *(const u64*)(We1 + k0);  // row 0 = dist weight pair

    u64 cr[4], acc[4];
#pragma unroll
    for (int n = 0; n < 4; n++) {
        cr[n] = *(const u64*)(g_c + (node0 + rg * 4 + n) * Hc + k0);
        acc[n] = 0ull;
    }

    // ---- stage full dist tile: 8 recv x 512 senders, duplicated pairs ----
    {
        const float* drow = g_dist + (size_t)node0 * Pc;
#pragma unroll
        for (int j = 0; j < 16; j++) {
            int i = t + j * 256;
            float d = drow[(i >> 9) * Pc + (i & (Pc - 1))];
            sbig[i] = pack2(d, d);
        }
    }
    __syncthreads();

    // ---- main loop: 256 senders / thread, pairs, branch-free depth-2 ----
    const float* arow = g_a + (b * Pc + hf * 256) * Hc + k0;
    const u64* dbase = sbig + (rg * 4) * Pc + hf * 256;

    u64 av0 = *(const u64*)(arow);
    u64 av1 = *(const u64*)(arow + Hc);
#pragma unroll 4
    for (int ss = 0; ss < 256; ss += 2) {
        // wrapped prefetch: always in-bounds; dead on the final iteration
        u64 nx0 = *(const u64*)(arow + ((ss + 2) & 255) * Hc);
        u64 nx1 = *(const u64*)(arow + ((ss + 3) & 255) * Hc);
#pragma unroll
        for (int n = 0; n < 4; n++) {
            ulonglong2 dp = *(const ulonglong2*)(dbase + n * Pc + ss);
            u64 p0 = fma2(dp.x, w0, add2(av0, cr[n]));
            u64 p1 = fma2(dp.y, w0, add2(av1, cr[n]));
            acc[n] = add2(acc[n], relu2(p0));
            acc[n] = add2(acc[n], relu2(p1));
        }
        av0 = nx0; av1 = nx1;
    }

    // ---- cross-half reduce (reuse sbig) + exact self-term removal ----
    __syncthreads();
#pragma unroll
    for (int n = 0; n < 4; n++)
        PBUF(hf, rg * 4 + n, kp) = acc[n];
    __syncthreads();

#pragma unroll
    for (int j = 0; j < 2; j++) {
        int idx = t + j * 256;        // 0..511
        int rcv = idx >> 6;
        int kx  = idx & 63;
        u64 s = add2(PBUF(0, rcv, kx), PBUF(1, rcv, kx));
        int kk = kx * 2;
        float lo, hi; unpack2(s, lo, hi);
        // s == r term: dist(r,r) == 0 exactly -> relu(a_r + c_r), exact
        const float* ap = g_a + (node0 + rcv) * Hc + kk;
        const float* cp = g_c + (node0 + rcv) * Hc + kk;
        Hs[rcv][kk]     = lo - fmaxf(ap[0] + cp[0], 0.f);
        Hs[rcv][kk + 1] = hi - fmaxf(ap[1] + cp[1], 0.f);
    }
    __syncthreads();   // PBUF fully consumed before nin (aliased) is written

    // node features into nin[:, 64:80]
    if (t < 128)
        nin[(t >> 4) * (Ec + Dc) + Ec + (t & 15)] = h[node0 * Dc + t];
    __syncthreads();

    // ---- Phase A: agg = hsum @ We2 + 511*be2.  thread = (j, node-pair) ----
    {
        int j = t & 63;
        int n0 = (t >> 6) * 2, n1 = n0 + 1;
        float b2 = 511.0f * be2[j];
        float a0 = b2, a1 = b2;
#pragma unroll 8
        for (int kk = 0; kk < Hc; kk += 4) {
            float w0s = We2[(kk + 0) * Ec + j];
            float w1s = We2[(kk + 1) * Ec + j];
            float w2s = We2[(kk + 2) * Ec + j];
            float w3s = We2[(kk + 3) * Ec + j];
            float4 v0 = *((const float4*)&Hs[n0][0] + (kk >> 2));
            float4 v1 = *((const float4*)&Hs[n1][0] + (kk >> 2));
            a0 = fmaf(v0.x, w0s, a0); a0 = fmaf(v0.y, w1s, a0);
            a0 = fmaf(v0.z, w2s, a0); a0 = fmaf(v0.w, w3s, a0);
            a1 = fmaf(v1.x, w0s, a1); a1 = fmaf(v1.y, w1s, a1);
            a1 = fmaf(v1.z, w2s, a1); a1 = fmaf(v1.w, w3s, a1);
        }
        nin[n0 * (Ec + Dc) + j] = a0;
        nin[n1 * (Ec + Dc) + j] = a1;
    }
    __syncthreads();

    // ---- Phase B: hidden layer. thread = (hidden unit, node-half) ----
    {
        int hu = t & 127, g = t >> 7;
        float b1 = bn1[hu];
        float accs[4];
#pragma unroll
        for (int m = 0; m < 4; m++) accs[m] = b1;
#pragma unroll 5
        for (int i = 0; i < Ec + Dc; i += 4) {
            float w0s = Wn1[(i + 0) * Hc + hu];
            float w1s = Wn1[(i + 1) * Hc + hu];
            float w2s = Wn1[(i + 2) * Hc + hu];
            float w3s = Wn1[(i + 3) * Hc + hu];
#pragma unroll
            for (int m = 0; m < 4; m++) {
                float4 v = *((const float4*)(nin + (g * 4 + m) * (Ec + Dc)) + (i >> 2));
                accs[m] = fmaf(v.x, w0s, accs[m]);
                accs[m] = fmaf(v.y, w1s, accs[m]);
                accs[m] = fmaf(v.z, w2s, accs[m]);
                accs[m] = fmaf(v.w, w3s, accs[m]);
            }
        }
#pragma unroll
        for (int m = 0; m < 4; m++)
            hid[(g * 4 + m) * Hc + hu] = fmaxf(accs[m], 0.f);
    }
    __syncthreads();

    // ---- Phase C: output layer. 128 threads = (node, dim) ----
    if (t < 128) {
        int n = t >> 4, d = t & 15;
        float a0 = 0.f, a1 = 0.f, a2 = 0.f, a3 = 0.f;
#pragma unroll 8
        for (int kk = 0; kk < Hc; kk += 4) {
            float4 v = *((const float4*)(hid + n * Hc) + (kk >> 2));
            a0 = fmaf(v.x, Wn2[(kk + 0) * Dc + d], a0);
            a1 = fmaf(v.y, Wn2[(kk + 1) * Dc + d], a1);
            a2 = fmaf(v.z, Wn2[(kk + 2) * Dc + d], a2);
            a3 = fmaf(v.w, Wn2[(kk + 3) * Dc + d], a3);
        }
        out[node0 * Dc + t] = bn2[d] + ((a0 + a1) + (a2 + a3));
    }
#undef PBUF
}

// ---------------------------------------------------------------------------
extern "C" void kernel_launch(void* const* d_in, const int* in_sizes, int n_in,
                              void* d_out, int out_size) {
    const float* h   = (const float*)d_in[0];
    const float* We1 = (const float*)d_in[1];
    const float* be1 = (const float*)d_in[2];
    const float* We2 = (const float*)d_in[3];
    const float* be2 = (const float*)d_in[4];
    const float* Wn1 = (const float*)d_in[5];
    const float* bn1 = (const float*)d_in[6];
    const float* Wn2 = (const float*)d_in[7];
    const float* bn2 = (const float*)d_in[8];
    float* out = (float*)d_out;

    predist_kernel<<<Bc * 32, 256>>>(h, We1, be1);
    edgepost_kernel<<<Bc * 64, 256>>>(h, We1, We2, be2, Wn1, bn1, Wn2, bn2, out);
}

// round 9
// speedup vs baseline: 1.0420x; 1.0420x over previous
#include <cuda_runtime.h>

#define Bc 8
#define Pc 512
#define Dc 16
#define Ec 64
#define Hc 128

typedef unsigned long long u64;

// Scratch (no allocations allowed -> __device__ globals)
__device__ float g_a[Bc * Pc * Hc];     // a_s = ns @ We1[17:33]          (2 MB)
__device__ float g_c[Bc * Pc * Hc];     // c_r = nr @ We1[1:17] + be1     (2 MB)
__device__ float g_dist[Bc * Pc * Pc];  // dist[b][r][s]                  (8 MB)

// ---------------- packed f32x2 helpers (sm_103a) ----------------
__device__ __forceinline__ u64 add2(u64 a, u64 b) {
    u64 r; asm("add.rn.f32x2 %0,%1,%2;" : "=l"(r) : "l"(a), "l"(b)); return r;
}
__device__ __forceinline__ u64 fma2(u64 a, u64 b, u64 c) {
    u64 r; asm("fma.rn.f32x2 %0,%1,%2,%3;" : "=l"(r) : "l"(a), "l"(b), "l"(c)); return r;
}
__device__ __forceinline__ u64 pack2(float lo, float hi) {
    u64 r; asm("mov.b64 %0,{%1,%2};" : "=l"(r) : "f"(lo), "f"(hi)); return r;
}
__device__ __forceinline__ void unpack2(u64 x, float& lo, float& hi) {
    asm("mov.b64 {%0,%1},%2;" : "=f"(lo), "=f"(hi) : "l"(x));
}
__device__ __forceinline__ u64 relu2(u64 x) {
    float lo, hi; unpack2(x, lo, hi);
    return pack2(fmaxf(lo, 0.f), fmaxf(hi, 0.f));
}

// ---------------------------------------------------------------------------
// K1 (fused pre+dist): grid = (b, 16-receiver chunk) = 8*32, 256 threads.
// ---------------------------------------------------------------------------
__global__ void __launch_bounds__(256)
predist_kernel(const float* __restrict__ h,
               const float* __restrict__ We1,
               const float* __restrict__ be1) {
    int b = blockIdx.x >> 5;
    int rc = blockIdx.x & 31;
    int t = threadIdx.x;

    __shared__ float nd[Pc][Dc + 1];  // 34.8 KB, pad kills conflicts

    for (int i = t; i < Pc * Dc; i += 256)
        nd[i >> 4][i & 15] = h[b * Pc * Dc + i];
    __syncthreads();

    // ---- a, c for nodes rc*16 .. rc*16+15 ----
    {
        int k = t & 127;
        int ng = t >> 7;               // 0/1 -> 8 nodes each
        int n0 = rc * 16 + ng * 8;
        float a[8], c[8];
        float b1 = be1[k];
#pragma unroll
        for (int n = 0; n < 8; n++) { a[n] = 0.f; c[n] = b1; }
#pragma unroll
        for (int d = 0; d < Dc; d++) {
            float ws = We1[(17 + d) * Hc + k];
            float wr = We1[(1 + d) * Hc + k];
#pragma unroll
            for (int n = 0; n < 8; n++) {
                float x = nd[n0 + n][d];
                a[n] = fmaf(x, ws, a[n]);
                c[n] = fmaf(x, wr, c[n]);
            }
        }
#pragma unroll
        for (int n = 0; n < 8; n++) {
            g_a[(b * Pc + n0 + n) * Hc + k] = a[n];
            g_c[(b * Pc + n0 + n) * Hc + k] = c[n];
        }
    }

    // ---- dist rows: 16 receivers x 512 senders ----
    for (int idx = t; idx < 16 * Pc; idx += 256) {
        int r = rc * 16 + (idx >> 9);
        int s = idx & (Pc - 1);
        float acc = 0.f;
#pragma unroll
        for (int d = 0; d < Dc; d++) {
            float df = nd[r][d] - nd[s][d];
            acc = fmaf(df, df, acc);
        }
        g_dist[(b * Pc + r) * Pc + s] = sqrtf(acc);
    }
}

// ---------------------------------------------------------------------------
// K2 (fused edge+post): grid = 512 (b, 8 receivers), 256 threads.
// Thread = (sender-half hf[0..1], recv-group rg[0..1], k-pair kp[0..63]).
// Main loop: batch-4 double-buffered register ring on av (MLP=8 per thread,
// prefetch distance = one full compute block), dist via LDS.128 broadcast.
// ---------------------------------------------------------------------------
__global__ void __launch_bounds__(256, 4)
edgepost_kernel(const float* __restrict__ h,
                const float* __restrict__ We1,
                const float* __restrict__ We2,
                const float* __restrict__ be2,
                const float* __restrict__ Wn1,
                const float* __restrict__ bn1,
                const float* __restrict__ Wn2,
                const float* __restrict__ bn2,
                float* __restrict__ out) {
    int b = blockIdx.x >> 6;
    int r0 = (blockIdx.x & 63) * 8;
    int node0 = b * Pc + r0;
    int t = threadIdx.x;
    int kp = t & 63;           // k-pair: k = 2*kp, 2*kp+1
    int rg = (t >> 6) & 1;     // receiver group (4 each)
    int hf = t >> 7;           // sender half (256 each)
    int k0 = kp * 2;

    __shared__ __align__(16) u64 sbig[8 * Pc];    // 32 KB: dist tile -> partials/nin/hid
#define PBUF(hh, r, x) sbig[(((hh) * 8 + (r)) << 6) + (x)]
    __shared__ __align__(16) float Hs[8][Hc];     // 4 KB
    float* nin = (float*)((char*)sbig + 8192);    // 8 x 80 floats (2.5 KB), past PBUF
    float* hid = (float*)((char*)sbig + 8192 + 2560);  // 8 x 128 floats (4 KB)

    u64 w0 = *(const u64*)(We1 + k0);  // row 0 = dist weight pair

    u64 cr[4], acc[4];
#pragma unroll
    for (int n = 0; n < 4; n++) {
        cr[n] = *(const u64*)(g_c + (node0 + rg * 4 + n) * Hc + k0);
        acc[n] = 0ull;
    }

    // ---- stage full dist tile: 8 recv x 512 senders, duplicated pairs ----
    {
        const float* drow = g_dist + (size_t)node0 * Pc;
#pragma unroll
        for (int j = 0; j < 16; j++) {
            int i = t + j * 256;
            float d = drow[(i >> 9) * Pc + (i & (Pc - 1))];
            sbig[i] = pack2(d, d);
        }
    }
    __syncthreads();

    // ---- main loop: 256 senders / thread, batch-4 double-buffer ring ----
    const float* arow = g_a + (b * Pc + hf * 256) * Hc + k0;
    const u64* dbase = sbig + (rg * 4) * Pc + hf * 256;

    u64 bA[4], bB[4];
#pragma unroll
    for (int i = 0; i < 4; i++)
        bA[i] = *(const u64*)(arow + i * Hc);

#pragma unroll 2
    for (int ss = 0; ss < 256; ss += 8) {
        // prefetch batch B (senders ss+4..ss+7); wrapped, dead on final iter
#pragma unroll
        for (int i = 0; i < 4; i++)
            bB[i] = *(const u64*)(arow + ((ss + 4 + i) & 255) * Hc);
        // compute senders ss..ss+3 with A
#pragma unroll
        for (int n = 0; n < 4; n++) {
            ulonglong2 d01 = *(const ulonglong2*)(dbase + n * Pc + ss);
            ulonglong2 d23 = *(const ulonglong2*)(dbase + n * Pc + ss + 2);
            u64 p0 = fma2(d01.x, w0, add2(bA[0], cr[n]));
            u64 p1 = fma2(d01.y, w0, add2(bA[1], cr[n]));
            u64 p2 = fma2(d23.x, w0, add2(bA[2], cr[n]));
            u64 p3 = fma2(d23.y, w0, add2(bA[3], cr[n]));
            acc[n] = add2(acc[n], add2(add2(relu2(p0), relu2(p1)),
                                       add2(relu2(p2), relu2(p3))));
        }
        // prefetch batch A (senders ss+8..ss+11); wrapped
#pragma unroll
        for (int i = 0; i < 4; i++)
            bA[i] = *(const u64*)(arow + ((ss + 8 + i) & 255) * Hc);
        // compute senders ss+4..ss+7 with B
#pragma unroll
        for (int n = 0; n < 4; n++) {
            ulonglong2 d01 = *(const ulonglong2*)(dbase + n * Pc + ss + 4);
            ulonglong2 d23 = *(const ulonglong2*)(dbase + n * Pc + ss + 6);
            u64 p0 = fma2(d01.x, w0, add2(bB[0], cr[n]));
            u64 p1 = fma2(d01.y, w0, add2(bB[1], cr[n]));
            u64 p2 = fma2(d23.x, w0, add2(bB[2], cr[n]));
            u64 p3 = fma2(d23.y, w0, add2(bB[3], cr[n]));
            acc[n] = add2(acc[n], add2(add2(relu2(p0), relu2(p1)),
                                       add2(relu2(p2), relu2(p3))));
        }
    }

    // ---- cross-half reduce (reuse sbig) + exact self-term removal ----
    __syncthreads();
#pragma unroll
    for (int n = 0; n < 4; n++)
        PBUF(hf, rg * 4 + n, kp) = acc[n];
    __syncthreads();

#pragma unroll
    for (int j = 0; j < 2; j++) {
        int idx = t + j * 256;        // 0..511
        int rcv = idx >> 6;
        int kx  = idx & 63;
        u64 s = add2(PBUF(0, rcv, kx), PBUF(1, rcv, kx));
        int kk = kx * 2;
        float lo, hi; unpack2(s, lo, hi);
        // s == r term: dist(r,r) == 0 exactly -> relu(a_r + c_r), exact
        const float* ap = g_a + (node0 + rcv) * Hc + kk;
        const float* cp = g_c + (node0 + rcv) * Hc + kk;
        Hs[rcv][kk]     = lo - fmaxf(ap[0] + cp[0], 0.f);
        Hs[rcv][kk + 1] = hi - fmaxf(ap[1] + cp[1], 0.f);
    }
    __syncthreads();   // PBUF fully consumed before nin (aliased) is written

    // node features into nin[:, 64:80]
    if (t < 128)
        nin[(t >> 4) * (Ec + Dc) + Ec + (t & 15)] = h[node0 * Dc + t];
    __syncthreads();

    // ---- Phase A: agg = hsum @ We2 + 511*be2.  thread = (j, node-pair) ----
    {
        int j = t & 63;
        int n0 = (t >> 6) * 2, n1 = n0 + 1;
        float b2 = 511.0f * be2[j];
        float a0 = b2, a1 = b2;
#pragma unroll 8
        for (int kk = 0; kk < Hc; kk += 4) {
            float w0s = We2[(kk + 0) * Ec + j];
            float w1s = We2[(kk + 1) * Ec + j];
            float w2s = We2[(kk + 2) * Ec + j];
            float w3s = We2[(kk + 3) * Ec + j];
            float4 v0 = *((const float4*)&Hs[n0][0] + (kk >> 2));
            float4 v1 = *((const float4*)&Hs[n1][0] + (kk >> 2));
            a0 = fmaf(v0.x, w0s, a0); a0 = fmaf(v0.y, w1s, a0);
            a0 = fmaf(v0.z, w2s, a0); a0 = fmaf(v0.w, w3s, a0);
            a1 = fmaf(v1.x, w0s, a1); a1 = fmaf(v1.y, w1s, a1);
            a1 = fmaf(v1.z, w2s, a1); a1 = fmaf(v1.w, w3s, a1);
        }
        nin[n0 * (Ec + Dc) + j] = a0;
        nin[n1 * (Ec + Dc) + j] = a1;
    }
    __syncthreads();

    // ---- Phase B: hidden layer. thread = (hidden unit, node-half) ----
    {
        int hu = t & 127, g = t >> 7;
        float b1 = bn1[hu];
        float accs[4];
#pragma unroll
        for (int m = 0; m < 4; m++) accs[m] = b1;
#pragma unroll 5
        for (int i = 0; i < Ec + Dc; i += 4) {
            float w0s = Wn1[(i + 0) * Hc + hu];
            float w1s = Wn1[(i + 1) * Hc + hu];
            float w2s = Wn1[(i + 2) * Hc + hu];
            float w3s = Wn1[(i + 3) * Hc + hu];
#pragma unroll
            for (int m = 0; m < 4; m++) {
                float4 v = *((const float4*)(nin + (g * 4 + m) * (Ec + Dc)) + (i >> 2));
                accs[m] = fmaf(v.x, w0s, accs[m]);
                accs[m] = fmaf(v.y, w1s, accs[m]);
                accs[m] = fmaf(v.z, w2s, accs[m]);
                accs[m] = fmaf(v.w, w3s, accs[m]);
            }
        }
#pragma unroll
        for (int m = 0; m < 4; m++)
            hid[(g * 4 + m) * Hc + hu] = fmaxf(accs[m], 0.f);
    }
    __syncthreads();

    // ---- Phase C: output layer. 128 threads = (node, dim) ----
    if (t < 128) {
        int n = t >> 4, d = t & 15;
        float a0 = 0.f, a1 = 0.f, a2 = 0.f, a3 = 0.f;
#pragma unroll 8
        for (int kk = 0; kk < Hc; kk += 4) {
            float4 v = *((const float4*)(hid + n * Hc) + (kk >> 2));
            a0 = fmaf(v.x, Wn2[(kk + 0) * Dc + d], a0);
            a1 = fmaf(v.y, Wn2[(kk + 1) * Dc + d], a1);
            a2 = fmaf(v.z, Wn2[(kk + 2) * Dc + d], a2);
            a3 = fmaf(v.w, Wn2[(kk + 3) * Dc + d], a3);
        }
        out[node0 * Dc + t] = bn2[d] + ((a0 + a1) + (a2 + a3));
    }
#undef PBUF
}

// ---------------------------------------------------------------------------
extern "C" void kernel_launch(void* const* d_in, const int* in_sizes, int n_in,
                              void* d_out, int out_size) {
    const float* h   = (const float*)d_in[0];
    const float* We1 = (const float*)d_in[1];
    const float* be1 = (const float*)d_in[2];
    const float* We2 = (const float*)d_in[3];
    const float* be2 = (const float*)d_in[4];
    const float* Wn1 = (const float*)d_in[5];
    const float* bn1 = (const float*)d_in[6];
    const float* Wn2 = (const float*)d_in[7];
    const float* bn2 = (const float*)d_in[8];
    float* out = (float*)d_out;

    predist_kernel<<<Bc * 32, 256>>>(h, We1, be1);
    edgepost_kernel<<<Bc * 64, 256>>>(h, We1, We2, be2, Wn1, bn1, Wn2, bn2, out);
}

// round 10
// speedup vs baseline: 1.0832x; 1.0395x over previous
#include <cuda_runtime.h>

#define Bc 8
#define Pc 512
#define Dc 16
#define Ec 64
#define Hc 128

typedef unsigned long long u64;

// Scratch (no allocations allowed -> __device__ globals)
__device__ float g_a[Bc * Pc * Hc];     // a_s = ns @ We1[17:33]          (2 MB)
__device__ float g_c[Bc * Pc * Hc];     // c_r = nr @ We1[1:17] + be1     (2 MB)
__device__ float g_dist[Bc * Pc * Pc];  // dist[b][r][s]                  (8 MB)

// ---------------- packed f32x2 helpers (sm_103a) ----------------
__device__ __forceinline__ u64 add2(u64 a, u64 b) {
    u64 r; asm("add.rn.f32x2 %0,%1,%2;" : "=l"(r) : "l"(a), "l"(b)); return r;
}
__device__ __forceinline__ u64 fma2(u64 a, u64 b, u64 c) {
    u64 r; asm("fma.rn.f32x2 %0,%1,%2,%3;" : "=l"(r) : "l"(a), "l"(b), "l"(c)); return r;
}
__device__ __forceinline__ u64 pack2(float lo, float hi) {
    u64 r; asm("mov.b64 %0,{%1,%2};" : "=l"(r) : "f"(lo), "f"(hi)); return r;
}
__device__ __forceinline__ void unpack2(u64 x, float& lo, float& hi) {
    asm("mov.b64 {%0,%1},%2;" : "=f"(lo), "=f"(hi) : "l"(x));
}
// max(q, thresh) elementwise on a packed pair; pack/unpack are reg aliasing
__device__ __forceinline__ u64 max2t(u64 q, float tl, float th) {
    float lo, hi; unpack2(q, lo, hi);
    return pack2(fmaxf(lo, tl), fmaxf(hi, th));
}

// ---------------------------------------------------------------------------
// K1 (fused pre+dist): grid = (b, 16-receiver chunk) = 8*32, 256 threads.
// ---------------------------------------------------------------------------
__global__ void __launch_bounds__(256)
predist_kernel(const float* __restrict__ h,
               const float* __restrict__ We1,
               const float* __restrict__ be1) {
    int b = blockIdx.x >> 5;
    int rc = blockIdx.x & 31;
    int t = threadIdx.x;

    __shared__ float nd[Pc][Dc + 1];  // 34.8 KB, pad kills conflicts

    for (int i = t; i < Pc * Dc; i += 256)
        nd[i >> 4][i & 15] = h[b * Pc * Dc + i];
    __syncthreads();

    // ---- a, c for nodes rc*16 .. rc*16+15 ----
    {
        int k = t & 127;
        int ng = t >> 7;               // 0/1 -> 8 nodes each
        int n0 = rc * 16 + ng * 8;
        float a[8], c[8];
        float b1 = be1[k];
#pragma unroll
        for (int n = 0; n < 8; n++) { a[n] = 0.f; c[n] = b1; }
#pragma unroll
        for (int d = 0; d < Dc; d++) {
            float ws = We1[(17 + d) * Hc + k];
            float wr = We1[(1 + d) * Hc + k];
#pragma unroll
            for (int n = 0; n < 8; n++) {
                float x = nd[n0 + n][d];
                a[n] = fmaf(x, ws, a[n]);
                c[n] = fmaf(x, wr, c[n]);
            }
        }
#pragma unroll
        for (int n = 0; n < 8; n++) {
            g_a[(b * Pc + n0 + n) * Hc + k] = a[n];
            g_c[(b * Pc + n0 + n) * Hc + k] = c[n];
        }
    }

    // ---- dist rows: 16 receivers x 512 senders ----
    for (int idx = t; idx < 16 * Pc; idx += 256) {
        int r = rc * 16 + (idx >> 9);
        int s = idx & (Pc - 1);
        float acc = 0.f;
#pragma unroll
        for (int d = 0; d < Dc; d++) {
            float df = nd[r][d] - nd[s][d];
            acc = fmaf(df, df, acc);
        }
        g_dist[(b * Pc + r) * Pc + s] = sqrtf(acc);
    }
}

// ---------------------------------------------------------------------------
// K2 (fused edge+post): grid = 512 (b, 8 receivers), 256 threads.
// Thread = (sender-half hf[0..1], recv-group rg[0..1], k-pair kp[0..63]).
// Inner math uses the hoisted-threshold identity:
//   relu(d*w0 + a + c) = max(fma(d,w0,a), -c) + c   (bit-exact)
// so the sum needs only fma2 + 2*FMNMX + tree-add2 per pair; the +c term is
// applied once per receiver as +511*c in the epilogue (self term folds in).
// ---------------------------------------------------------------------------
__global__ void __launch_bounds__(256, 4)
edgepost_kernel(const float* __restrict__ h,
                const float* __restrict__ We1,
                const float* __restrict__ We2,
                const float* __restrict__ be2,
                const float* __restrict__ Wn1,
                const float* __restrict__ bn1,
                const float* __restrict__ Wn2,
                const float* __restrict__ bn2,
                float* __restrict__ out) {
    int b = blockIdx.x >> 6;
    int r0 = (blockIdx.x & 63) * 8;
    int node0 = b * Pc + r0;
    int t = threadIdx.x;
    int kp = t & 63;           // k-pair: k = 2*kp, 2*kp+1
    int rg = (t >> 6) & 1;     // receiver group (4 each)
    int hf = t >> 7;           // sender half (256 each)
    int k0 = kp * 2;

    __shared__ __align__(16) u64 sbig[8 * Pc];    // 32 KB: dist tile -> partials/nin/hid
#define PBUF(hh, r, x) sbig[(((hh) * 8 + (r)) << 6) + (x)]
    __shared__ __align__(16) float Hs[8][Hc];     // 4 KB
    float* nin = (float*)((char*)sbig + 8192);    // 8 x 80 floats (2.5 KB), past PBUF
    float* hid = (float*)((char*)sbig + 8192 + 2560);  // 8 x 128 floats (4 KB)

    u64 w0 = *(const u64*)(We1 + k0);  // row 0 = dist weight pair

    float ncl[4], nch[4];              // negated c halves (loop thresholds)
    u64 acc[4];
#pragma unroll
    for (int n = 0; n < 4; n++) {
        const float* cp = g_c + (node0 + rg * 4 + n) * Hc + k0;
        ncl[n] = -cp[0];
        nch[n] = -cp[1];
        acc[n] = 0ull;
    }

    // ---- stage full dist tile: 8 recv x 512 senders, duplicated pairs ----
    {
        const float* drow = g_dist + (size_t)node0 * Pc;
#pragma unroll
        for (int j = 0; j < 16; j++) {
            int i = t + j * 256;
            float d = drow[(i >> 9) * Pc + (i & (Pc - 1))];
            sbig[i] = pack2(d, d);
        }
    }
    __syncthreads();

    // ---- main loop: 256 senders / thread, batch-4 double-buffer ring ----
    const float* arow = g_a + (b * Pc + hf * 256) * Hc + k0;
    const u64* dbase = sbig + (rg * 4) * Pc + hf * 256;

    u64 bA[4], bB[4];
#pragma unroll
    for (int i = 0; i < 4; i++)
        bA[i] = *(const u64*)(arow + i * Hc);

#pragma unroll 2
    for (int ss = 0; ss < 256; ss += 8) {
        // prefetch batch B (senders ss+4..ss+7); wrapped, dead on final iter
#pragma unroll
        for (int i = 0; i < 4; i++)
            bB[i] = *(const u64*)(arow + ((ss + 4 + i) & 255) * Hc);
        // compute senders ss..ss+3 with A
#pragma unroll
        for (int n = 0; n < 4; n++) {
            ulonglong2 d01 = *(const ulonglong2*)(dbase + n * Pc + ss);
            ulonglong2 d23 = *(const ulonglong2*)(dbase + n * Pc + ss + 2);
            u64 m0 = max2t(fma2(d01.x, w0, bA[0]), ncl[n], nch[n]);
            u64 m1 = max2t(fma2(d01.y, w0, bA[1]), ncl[n], nch[n]);
            u64 m2 = max2t(fma2(d23.x, w0, bA[2]), ncl[n], nch[n]);
            u64 m3 = max2t(fma2(d23.y, w0, bA[3]), ncl[n], nch[n]);
            acc[n] = add2(acc[n], add2(add2(m0, m1), add2(m2, m3)));
        }
        // prefetch batch A (senders ss+8..ss+11); wrapped
#pragma unroll
        for (int i = 0; i < 4; i++)
            bA[i] = *(const u64*)(arow + ((ss + 8 + i) & 255) * Hc);
        // compute senders ss+4..ss+7 with B
#pragma unroll
        for (int n = 0; n < 4; n++) {
            ulonglong2 d01 = *(const ulonglong2*)(dbase + n * Pc + ss + 4);
            ulonglong2 d23 = *(const ulonglong2*)(dbase + n * Pc + ss + 6);
            u64 m0 = max2t(fma2(d01.x, w0, bB[0]), ncl[n], nch[n]);
            u64 m1 = max2t(fma2(d01.y, w0, bB[1]), ncl[n], nch[n]);
            u64 m2 = max2t(fma2(d23.x, w0, bB[2]), ncl[n], nch[n]);
            u64 m3 = max2t(fma2(d23.y, w0, bB[3]), ncl[n], nch[n]);
            acc[n] = add2(acc[n], add2(add2(m0, m1), add2(m2, m3)));
        }
    }

    // ---- cross-half reduce (reuse sbig) + epilogue correction ----
    __syncthreads();
#pragma unroll
    for (int n = 0; n < 4; n++)
        PBUF(hf, rg * 4 + n, kp) = acc[n];
    __syncthreads();

#pragma unroll
    for (int j = 0; j < 2; j++) {
        int idx = t + j * 256;        // 0..511
        int rcv = idx >> 6;
        int kx  = idx & 63;
        u64 s = add2(PBUF(0, rcv, kx), PBUF(1, rcv, kx));
        int kk = kx * 2;
        float lo, hi; unpack2(s, lo, hi);
        // hsum = Sum_all max(q_s,-c) - max(a_r,-c) + 511*c
        // (self sender q = fma(0,w0,a_r) = a_r exactly; +c hoisted: 512-1 = 511)
        const float* ap = g_a + (node0 + rcv) * Hc + kk;
        const float* cp = g_c + (node0 + rcv) * Hc + kk;
        Hs[rcv][kk]     = fmaf(511.0f, cp[0], lo - fmaxf(ap[0], -cp[0]));
        Hs[rcv][kk + 1] = fmaf(511.0f, cp[1], hi - fmaxf(ap[1], -cp[1]));
    }
    __syncthreads();   // PBUF fully consumed before nin (aliased) is written

    // node features into nin[:, 64:80]
    if (t < 128)
        nin[(t >> 4) * (Ec + Dc) + Ec + (t & 15)] = h[node0 * Dc + t];
    __syncthreads();

    // ---- Phase A: agg = hsum @ We2 + 511*be2.  thread = (j, node-pair) ----
    {
        int j = t & 63;
        int n0 = (t >> 6) * 2, n1 = n0 + 1;
        float b2 = 511.0f * be2[j];
        float a0 = b2, a1 = b2;
#pragma unroll 8
        for (int kk = 0; kk < Hc; kk += 4) {
            float w0s = We2[(kk + 0) * Ec + j];
            float w1s = We2[(kk + 1) * Ec + j];
            float w2s = We2[(kk + 2) * Ec + j];
            float w3s = We2[(kk + 3) * Ec + j];
            float4 v0 = *((const float4*)&Hs[n0][0] + (kk >> 2));
            float4 v1 = *((const float4*)&Hs[n1][0] + (kk >> 2));
            a0 = fmaf(v0.x, w0s, a0); a0 = fmaf(v0.y, w1s, a0);
            a0 = fmaf(v0.z, w2s, a0); a0 = fmaf(v0.w, w3s, a0);
            a1 = fmaf(v1.x, w0s, a1); a1 = fmaf(v1.y, w1s, a1);
            a1 = fmaf(v1.z, w2s, a1); a1 = fmaf(v1.w, w3s, a1);
        }
        nin[n0 * (Ec + Dc) + j] = a0;
        nin[n1 * (Ec + Dc) + j] = a1;
    }
    __syncthreads();

    // ---- Phase B: hidden layer. thread = (hidden unit, node-half) ----
    {
        int hu = t & 127, g = t >> 7;
        float b1 = bn1[hu];
        float accs[4];
#pragma unroll
        for (int m = 0; m < 4; m++) accs[m] = b1;
#pragma unroll 5
        for (int i = 0; i < Ec + Dc; i += 4) {
            float w0s = Wn1[(i + 0) * Hc + hu];
            float w1s = Wn1[(i + 1) * Hc + hu];
            float w2s = Wn1[(i + 2) * Hc + hu];
            float w3s = Wn1[(i + 3) * Hc + hu];
#pragma unroll
            for (int m = 0; m < 4; m++) {
                float4 v = *((const float4*)(nin + (g * 4 + m) * (Ec + Dc)) + (i >> 2));
                accs[m] = fmaf(v.x, w0s, accs[m]);
                accs[m] = fmaf(v.y, w1s, accs[m]);
                accs[m] = fmaf(v.z, w2s, accs[m]);
                accs[m] = fmaf(v.w, w3s, accs[m]);
            }
        }
#pragma unroll
        for (int m = 0; m < 4; m++)
            hid[(g * 4 + m) * Hc + hu] = fmaxf(accs[m], 0.f);
    }
    __syncthreads();

    // ---- Phase C: output layer. 128 threads = (node, dim) ----
    if (t < 128) {
        int n = t >> 4, d = t & 15;
        float a0 = 0.f, a1 = 0.f, a2 = 0.f, a3 = 0.f;
#pragma unroll 8
        for (int kk = 0; kk < Hc; kk += 4) {
            float4 v = *((const float4*)(hid + n * Hc) + (kk >> 2));
            a0 = fmaf(v.x, Wn2[(kk + 0) * Dc + d], a0);
            a1 = fmaf(v.y, Wn2[(kk + 1) * Dc + d], a1);
            a2 = fmaf(v.z, Wn2[(kk + 2) * Dc + d], a2);
            a3 = fmaf(v.w, Wn2[(kk + 3) * Dc + d], a3);
        }
        out[node0 * Dc + t] = bn2[d] + ((a0 + a1) + (a2 + a3));
    }
#undef PBUF
}

// ---------------------------------------------------------------------------
extern "C" void kernel_launch(void* const* d_in, const int* in_sizes, int n_in,
                              void* d_out, int out_size) {
    const float* h   = (const float*)d_in[0];
    const float* We1 = (const float*)d_in[1];
    const float* be1 = (const float*)d_in[2];
    const float* We2 = (const float*)d_in[3];
    const float* be2 = (const float*)d_in[4];
    const float* Wn1 = (const float*)d_in[5];
    const float* bn1 = (const float*)d_in[6];
    const float* Wn2 = (const float*)d_in[7];
    const float* bn2 = (const float*)d_in[8];
    float* out = (float*)d_out;

    predist_kernel<<<Bc * 32, 256>>>(h, We1, be1);
    edgepost_kernel<<<Bc * 64, 256>>>(h, We1, We2, be2, Wn1, bn1, Wn2, bn2, out);
}